// round 10
// baseline (speedup 1.0000x reference)
#include <cuda_runtime.h>
#include <cstddef>

// Raster_87205015978273: per-depo 10x10x10 Gaussian raster patches.
// Output buffer (all float32): [N*1000] rasters, then [N*3] offsets (exact
// integer values stored as float).
//
// R10: 2 depos per warp. Both depos' scalar inputs are loaded up-front
// (MLP on the ~600-cycle LDGs), both weight sets computed, then 2x the
// store stream per warp prologue. All sync is __syncwarp.

#define WARPS   8
#define DPW     2                    // depos per warp
#define DPB     (WARPS * DPW)        // 16 depos per block
#define NTHREADS 256

__global__ __launch_bounds__(NTHREADS, 6)
void raster_kernel(const float* __restrict__ sigma,   // [N,3]
                   const float* __restrict__ time,    // [N]
                   const float* __restrict__ charge,  // [N]
                   const float* __restrict__ tail,    // [N,3]
                   const float* __restrict__ gs,      // [3]
                   const float* __restrict__ nsig,    // [1]
                   float* __restrict__ out_r,         // [N,10,10,10] f32
                   float* __restrict__ out_o,         // [N,3] offsets as f32
                   int N)
{
    __shared__ float  sw[WARPS][DPW][32];   // [w][dp][d*10+j]
    __shared__ float4 yz4[WARPS][DPW][25];  // [w][dp][jk/4]

    const int t    = threadIdx.x;
    const int wid  = t >> 5;
    const int lane = t & 31;
    const int n0   = blockIdx.x * DPB + wid * DPW;

    if (n0 < N) {
        // ---- Phase A: load both depos' inputs, then compute weights ----
        if (lane < 30) {
            const int d = lane / 10;      // dim 0,1,2
            const int j = lane - d * 10;  // cell 0..9
            const float h  = gs[d];
            const float ns = nsig[0];

            float c[DPW], sg[DPW], ch[DPW];
            #pragma unroll
            for (int dp = 0; dp < DPW; dp++) {
                const int n = n0 + dp;
                if (n < N) {
                    c[dp]  = (d == 0) ? tail[3 * n + 1]
                           : (d == 1) ? tail[3 * n + 2]
                                      : time[n];
                    sg[dp] = sigma[3 * n + d];
                    ch[dp] = charge[n];
                }
            }

            #pragma unroll
            for (int dp = 0; dp < DPW; dp++) {
                const int n = n0 + dp;
                if (n < N) {
                    const float imin = floorf((c[dp] - ns * sg[dp]) / h);
                    const float inv  = 1.0f / (1.41421356237309515f * sg[dp]);
                    const float e0 = (imin + (float)j) * h;
                    const float e1 = (imin + (float)(j + 1)) * h;
                    float w = 0.5f * (erff((e1 - c[dp]) * inv) - erff((e0 - c[dp]) * inv));
                    if (d == 0) w *= ch[dp];             // fold charge into x weights
                    sw[wid][dp][d * 10 + j] = w;
                    if (j == 0) out_o[3 * n + d] = imin; // offsets as float values
                }
            }
        }
        __syncwarp();

        // ---- Phase B: yz[jk] = wy[j]*wz[k] (200 values per warp) ----
        {
            float* yzf = (float*)&yz4[wid][0][0];   // 2*100 floats (rows are 400B apart)
            #pragma unroll
            for (int l = 0; l < 7; l++) {
                const int p = lane + (l << 5);      // 0..223
                if (l < 6 || p < 200) {
                    const int dp = p / 100;
                    const int rr = p - dp * 100;
                    const int jj = rr / 10;
                    const int kk = rr - jj * 10;
                    yzf[dp * 100 + rr] = sw[wid][dp][10 + jj] * sw[wid][dp][20 + kk];
                }
            }
        }
        __syncwarp();

        // ---- Phase C: 250 float4 streaming stores per depo, depth-4 batches ----
        #pragma unroll
        for (int dp = 0; dp < DPW; dp++) {
            const int n = n0 + dp;
            if (n >= N) break;
            float* dst = out_r + (size_t)n * 1000;

            #pragma unroll
            for (int half = 0; half < 2; half++) {
                float4 z[4];
                float  s[4];
                int    q4[4];

                #pragma unroll
                for (int l = 0; l < 4; l++) {
                    int q = lane + ((half * 4 + l) << 5);   // 0..255
                    q4[l] = q;
                    int qc = (q > 249) ? 249 : q;           // clamp tail
                    int i   = qc / 25;                      // x-slab (0..9)
                    int jk4 = qc - i * 25;                  // float4 in yz plane
                    z[l] = yz4[wid][dp][jk4];
                    s[l] = sw[wid][dp][i];                  // charge*wx[i]
                }

                #pragma unroll
                for (int l = 0; l < 4; l++) {
                    z[l].x *= s[l];
                    z[l].y *= s[l];
                    z[l].z *= s[l];
                    z[l].w *= s[l];
                }

                #pragma unroll
                for (int l = 0; l < 4; l++) {
                    if (half == 0 || l < 3 || q4[l] < 250) {
                        __stcs(reinterpret_cast<float4*>(dst + q4[l] * 4), z[l]);
                    }
                }
            }
        }
    }
}

extern "C" void kernel_launch(void* const* d_in, const int* in_sizes, int n_in,
                              void* d_out, int out_size)
{
    const float* sigma  = (const float*)d_in[0];
    const float* time   = (const float*)d_in[1];
    const float* charge = (const float*)d_in[2];
    const float* tail   = (const float*)d_in[3];
    const float* gs     = (const float*)d_in[4];
    const float* nsig   = (const float*)d_in[5];

    const int N = in_sizes[1];             // time has N elements
    float* out_r = (float*)d_out;
    float* out_o = out_r + (size_t)N * 1000;

    const int grid = (N + DPB - 1) / DPB;
    raster_kernel<<<grid, NTHREADS>>>(sigma, time, charge, tail, gs, nsig,
                                      out_r, out_o, N);
}